// round 9
// baseline (speedup 1.0000x reference)
#include <cuda_runtime.h>
#include <cuda_fp16.h>
#include <cstdint>

// ============================================================================
// BinaryConv2D: x(64,56,56,128) NHWC conv w(3,3,128,256) HWIO, SAME, stride 1.
// binarize both -> implicit GEMM on mma.sync m16n8k32 e4m3, F16 accumulate
// (exact: products ±1, partial sums are integers <= 1152 < 2048).
// CTA: 128 pixels (8h x 16w) x 128 outch. 256 threads, 8 warps (4M x 2N),
// warp tile 32 x 64, 3 CTAs/SM (85-reg budget, ~80 used).
//   A: SMEM halo 10x18 px, PADDED-LINEAR rows (144B stride, conflict-free,
//      NO xor-swizzle -> 1 IADD per ldmatrix address). Loaded once, no
//      mainloop barriers, tap loop ROLLED (R5/R7: unroll/big tiles => spill).
//   B: no smem; fragment-ordered weights, one k-step x two n-groups per
//      uint4; ALL 4 bv prefetched per k-step, then 16 dependency-free MMAs.
// Empirical wall: legacy QMMA rate => ~223us at tensor=100%; this round
// targets tensor% via ALU cut + LDG->MMA decoupling.
// (tcgen05/TMEM unavailable: harness ptxas targets base sm_103 — proven R1.)
// ============================================================================

constexpr int X_ELEMS = 64 * 56 * 56 * 128;   // 25,690,112
constexpr int WF_U4   = 9 * 4 * 16 * 32;      // 18,432 uint4 = 294,912 B
constexpr int X_BLOCKS = X_ELEMS / 8 / 256;   // 12,544

__device__ uint8_t g_xq[X_ELEMS];             // binarized x, NHWC e4m3
__device__ uint4   g_wf[WF_U4];               // weights, fragment-ordered

// ---------------------------------------------------------------------------
// merged preprocessing: e4m3 +1.0 = 0x38, -1.0 = 0xB8
// ---------------------------------------------------------------------------
__global__ void prep_kernel(const float* __restrict__ x,
                            const float* __restrict__ w) {
    if (blockIdx.x < X_BLOCKS) {
        int t = blockIdx.x * 256 + threadIdx.x;
        int base = t * 8;
        const float4* p = reinterpret_cast<const float4*>(x + base);
        float4 v0 = p[0], v1 = p[1];
        uint32_t lo = (v0.x >= 0.0f ? 0x38u : 0xB8u)        |
                      ((v0.y >= 0.0f ? 0x38u : 0xB8u) << 8)  |
                      ((v0.z >= 0.0f ? 0x38u : 0xB8u) << 16) |
                      ((v0.w >= 0.0f ? 0x38u : 0xB8u) << 24);
        uint32_t hi = (v1.x >= 0.0f ? 0x38u : 0xB8u)        |
                      ((v1.y >= 0.0f ? 0x38u : 0xB8u) << 8)  |
                      ((v1.z >= 0.0f ? 0x38u : 0xB8u) << 16) |
                      ((v1.w >= 0.0f ? 0x38u : 0xB8u) << 24);
        *reinterpret_cast<uint2*>(g_xq + base) = make_uint2(lo, hi);
    } else {
        // fragment order: u4 = ((tap*4 + k)*16 + gp)*32 + lane
        //   gp = n-group pair; {x,y} = B frag for o-group 2gp, {z,w} for 2gp+1
        //   o = g*8 + (lane>>2)
        //   b0 bytes b2: ch = k*32 + (lane&3)*4 + b2 ; b1: +16  (m16n8k32 colB)
        int u = (blockIdx.x - X_BLOCKS) * 256 + threadIdx.x;
        if (u >= WF_U4) return;
        int lane = u & 31;
        int gp   = (u >> 5) & 15;
        int k    = (u >> 9) & 3;
        int tap  = u >> 11;
        int cb = k * 32 + (lane & 3) * 4;
        uint32_t r[4];
        #pragma unroll
        for (int e = 0; e < 2; ++e) {
            int o = (2 * gp + e) * 8 + (lane >> 2);
            uint32_t r0 = 0, r1 = 0;
            #pragma unroll
            for (int b2 = 0; b2 < 4; ++b2) {
                float v0 = w[(tap * 128 + cb + b2) * 256 + o];       // HWIO
                float v1 = w[(tap * 128 + cb + 16 + b2) * 256 + o];
                r0 |= (v0 >= 0.0f ? 0x38u : 0xB8u) << (8 * b2);
                r1 |= (v1 >= 0.0f ? 0x38u : 0xB8u) << (8 * b2);
            }
            r[2 * e] = r0; r[2 * e + 1] = r1;
        }
        g_wf[u] = make_uint4(r[0], r[1], r[2], r[3]);
    }
}

// ---------------------------------------------------------------------------
// PTX helpers
// ---------------------------------------------------------------------------
static __device__ __forceinline__ void ldmatrix_x4(uint32_t& r0, uint32_t& r1,
                                                   uint32_t& r2, uint32_t& r3,
                                                   uint32_t addr) {
    asm volatile("ldmatrix.sync.aligned.m8n8.x4.shared.b16 {%0,%1,%2,%3}, [%4];"
                 : "=r"(r0), "=r"(r1), "=r"(r2), "=r"(r3) : "r"(addr));
}

// fp8 MMA with f16 accumulators (2 regs, exact for integer sums < 2048)
static __device__ __forceinline__ void mma_fp8_h(uint32_t* c, const uint32_t* a,
                                                 uint32_t b0, uint32_t b1) {
    asm volatile(
        "mma.sync.aligned.m16n8k32.row.col.f16.e4m3.e4m3.f16 "
        "{%0,%1}, {%2,%3,%4,%5}, {%6,%7}, {%0,%1};"
        : "+r"(c[0]), "+r"(c[1])
        : "r"(a[0]), "r"(a[1]), "r"(a[2]), "r"(a[3]), "r"(b0), "r"(b1));
}

static __device__ __forceinline__ void cp16(uint32_t dst, const void* src, int srcsize) {
    asm volatile("cp.async.cg.shared.global [%0], [%1], 16, %2;"
                 :: "r"(dst), "l"(src), "r"(srcsize) : "memory");
}

// ---------------------------------------------------------------------------
// main kernel: 256 threads, 8 warps (4M x 2N), warp tile 32x64
// SMEM: A halo, 180 rows x 144B stride (128B data + 16B pad) = 25920 B.
// Conflict-free without swizzle: chunk offset (9r + c) mod 8 distinct over
// the 8 rows of each ldmatrix sub-matrix.
// ---------------------------------------------------------------------------
constexpr int ROWB = 144;
constexpr int SMEM_TOTAL = 180 * ROWB;        // 25,920

__global__ void __launch_bounds__(256, 3)
conv_fp8_kernel(float* __restrict__ out) {
    extern __shared__ char smem[];
    uint32_t sbase = (uint32_t)__cvta_generic_to_shared(smem);

    int tid  = threadIdx.x;
    int lane = tid & 31;
    int wid  = tid >> 5;
    int warp_m = wid >> 1;       // 0..3 -> 32 pixel rows each
    int warp_n = wid & 1;        // 0..1 -> 64 outch each

    // tile decode: blockIdx = ((img*28 + ht*4 + wt) << 1) | ntile
    int b = blockIdx.x;
    int ntile = b & 1;
    int mt = b >> 1;
    int img = mt / 28;
    int rr  = mt - img * 28;
    int h0 = (rr >> 2) * 8;
    int w0 = (rr & 3) * 16;
    int n0 = ntile * 128;

    // ---- stage A halo (10h x 18w pixels, zero-filled outside image) ----
    for (int idx = tid; idx < 1440; idx += 256) {        // 180 rows x 8 chunks
        int row = idx >> 3, ch = idx & 7;
        int hr = row / 18;
        int wc = row - hr * 18;
        int hh = h0 + hr - 1;
        int ww = w0 + wc - 1;
        bool v = ((unsigned)hh < 56u) && ((unsigned)ww < 56u);
        const char* src = v ? (const char*)(g_xq + (((img * 56 + hh) * 56 + ww) << 7))
                            : (const char*)g_xq;
        cp16(sbase + row * ROWB + ch * 16, src + ch * 16, v ? 16 : 0);
    }
    asm volatile("cp.async.commit_group;" ::: "memory");
    asm volatile("cp.async.wait_group 0;" ::: "memory");
    __syncthreads();

    // ---- per-lane ldmatrix base addresses (linear layout: 1 IADD per use) ----
    int lane15 = lane & 15;
    int lanehi = lane >> 4;
    uint32_t abase[2];
    #pragma unroll
    for (int mi = 0; mi < 2; ++mi) {
        int p = warp_m * 32 + mi * 16 + lane15;          // pixel index 0..127
        int hrow = (p >> 4) * 18 + (p & 15);             // halo row at tap (0,0)
        abase[mi] = sbase + hrow * ROWB + lanehi * 16;
    }
    // B fragment base: gp base = ntile*8 + warp_n*4
    const uint4* wf0 = g_wf + (uint32_t)((ntile * 8 + warp_n * 4) * 32 + lane);

    uint32_t acc[2][8][2];                               // f16x2 accumulators
    #pragma unroll
    for (int mi = 0; mi < 2; ++mi)
        #pragma unroll
        for (int ni = 0; ni < 8; ++ni) {
            acc[mi][ni][0] = 0u; acc[mi][ni][1] = 0u;
        }

    // ---- mainloop: 9 taps (ROLLED) x 4 k-steps, no barriers ----
    int tapoff = 0;   // kh*18 + kw
    int kw = 0;
    for (int tap = 0; tap < 9; ++tap) {
        const uint4* wft = wf0 + (uint32_t)(tap * 2048);   // 4*16*32
        uint32_t toff = (uint32_t)(tapoff * ROWB);
        #pragma unroll
        for (int k = 0; k < 4; ++k) {
            // prefetch ALL B fragments for this k-step (4 x LDG.128)
            const uint4* wfk = wft + (uint32_t)(k * 512);  // 16*32
            uint4 bv0 = __ldg(wfk);
            uint4 bv1 = __ldg(wfk + 32);
            uint4 bv2 = __ldg(wfk + 64);
            uint4 bv3 = __ldg(wfk + 96);
            // A fragments (addresses: base + const per k)
            uint32_t a[2][4];
            #pragma unroll
            for (int mi = 0; mi < 2; ++mi)
                ldmatrix_x4(a[mi][0], a[mi][1], a[mi][2], a[mi][3],
                            abase[mi] + toff + (uint32_t)(k * 32));
            // 16 dependency-free MMAs
            mma_fp8_h(acc[0][0], a[0], bv0.x, bv0.y);
            mma_fp8_h(acc[0][1], a[0], bv0.z, bv0.w);
            mma_fp8_h(acc[1][0], a[1], bv0.x, bv0.y);
            mma_fp8_h(acc[1][1], a[1], bv0.z, bv0.w);
            mma_fp8_h(acc[0][2], a[0], bv1.x, bv1.y);
            mma_fp8_h(acc[0][3], a[0], bv1.z, bv1.w);
            mma_fp8_h(acc[1][2], a[1], bv1.x, bv1.y);
            mma_fp8_h(acc[1][3], a[1], bv1.z, bv1.w);
            mma_fp8_h(acc[0][4], a[0], bv2.x, bv2.y);
            mma_fp8_h(acc[0][5], a[0], bv2.z, bv2.w);
            mma_fp8_h(acc[1][4], a[1], bv2.x, bv2.y);
            mma_fp8_h(acc[1][5], a[1], bv2.z, bv2.w);
            mma_fp8_h(acc[0][6], a[0], bv3.x, bv3.y);
            mma_fp8_h(acc[0][7], a[0], bv3.z, bv3.w);
            mma_fp8_h(acc[1][6], a[1], bv3.x, bv3.y);
            mma_fp8_h(acc[1][7], a[1], bv3.z, bv3.w);
        }
        if (kw == 2) { kw = 0; tapoff += 16; }           // +18 - 2
        else         { kw++;   tapoff += 1;  }
    }

    // ---- epilogue: f16x2 -> f32 stores (exact, values are ints <= 1152) ----
    int colbase = n0 + warp_n * 64 + (lane & 3) * 2;
    #pragma unroll
    for (int mi = 0; mi < 2; ++mi) {
        #pragma unroll
        for (int half = 0; half < 2; ++half) {
            int p = warp_m * 32 + mi * 16 + half * 8 + (lane >> 2);
            int j = p & 15;
            int ww = w0 + j;
            if (ww >= 56) continue;
            int hh = h0 + (p >> 4);
            float* op = out + (((img * 56 + hh) * 56 + ww) << 8);
            #pragma unroll
            for (int ni = 0; ni < 8; ++ni) {
                __half2 h = *reinterpret_cast<__half2*>(&acc[mi][ni][half]);
                float2 v = __half22float2(h);
                *reinterpret_cast<float2*>(op + colbase + ni * 8) = v;
            }
        }
    }
}

// ---------------------------------------------------------------------------
// launch
// ---------------------------------------------------------------------------
extern "C" void kernel_launch(void* const* d_in, const int* in_sizes, int n_in,
                              void* d_out, int out_size) {
    const float* x = (const float*)d_in[0];
    const float* w = (const float*)d_in[1];
    float* out = (float*)d_out;

    prep_kernel<<<X_BLOCKS + (WF_U4 + 255) / 256, 256>>>(x, w);

    cudaFuncSetAttribute(conv_fp8_kernel,
                         cudaFuncAttributeMaxDynamicSharedMemorySize, SMEM_TOTAL);
    // 64 images * 7 h-tiles * 4 w-tiles * 2 n-tiles = 3584 CTAs
    conv_fp8_kernel<<<3584, 256, SMEM_TOTAL>>>(out);
}

// round 10
// speedup vs baseline: 4.1356x; 4.1356x over previous
#include <cuda_runtime.h>
#include <cuda_fp16.h>
#include <cstdint>

// ============================================================================
// BinaryConv2D: x(64,56,56,128) NHWC conv w(3,3,128,256) HWIO, SAME, stride 1.
// binarize both -> implicit GEMM on mma.sync m16n8k32 e4m3, F16 accumulate
// (exact: products ±1, partial sums are integers <= 1152 < 2048).
// == R6 structure EXACTLY (best: 364.6us) with ONE change: padded-linear SMEM
// (144B row stride, no xor-swizzle) to delete inner-loop address ALU. ==
// CTA: 128 pixels (8h x 16w) x 128 outch. 256 threads, 8 warps (4M x 2N),
// warp tile 32 x 64, 3 CTAs/SM.
//   A: SMEM halo 10x18 px, linear 144B-stride rows (conflict-free: 16*i mod
//      128 distinct for the 8 ldmatrix rows). No mainloop barriers, tap loop
//      ROLLED. A-address = per-tap base; k*32 folds into LDSM immediate.
//   B: no smem; fragment-ordered, uint4 = 2 k-steps x 1 n-group, __ldg right
//      before use (SHORT live ranges — R9 proved prefetch batching => spills
//      => 7GB local traffic => 4x regression).
// (tcgen05/TMEM unavailable: harness ptxas targets base sm_103 — proven R1.)
// ============================================================================

constexpr int X_ELEMS = 64 * 56 * 56 * 128;   // 25,690,112
constexpr int WF_U4   = 9 * 32 * 2 * 32;      // 18,432 uint4 = 294,912 B
constexpr int X_BLOCKS = X_ELEMS / 8 / 256;   // 12,544

__device__ uint8_t g_xq[X_ELEMS];             // binarized x, NHWC e4m3
__device__ uint4   g_wf[WF_U4];               // weights, fragment-ordered

// ---------------------------------------------------------------------------
// merged preprocessing: e4m3 +1.0 = 0x38, -1.0 = 0xB8
// ---------------------------------------------------------------------------
__global__ void prep_kernel(const float* __restrict__ x,
                            const float* __restrict__ w) {
    if (blockIdx.x < X_BLOCKS) {
        int t = blockIdx.x * 256 + threadIdx.x;
        int base = t * 8;
        const float4* p = reinterpret_cast<const float4*>(x + base);
        float4 v0 = p[0], v1 = p[1];
        uint32_t lo = (v0.x >= 0.0f ? 0x38u : 0xB8u)        |
                      ((v0.y >= 0.0f ? 0x38u : 0xB8u) << 8)  |
                      ((v0.z >= 0.0f ? 0x38u : 0xB8u) << 16) |
                      ((v0.w >= 0.0f ? 0x38u : 0xB8u) << 24);
        uint32_t hi = (v1.x >= 0.0f ? 0x38u : 0xB8u)        |
                      ((v1.y >= 0.0f ? 0x38u : 0xB8u) << 8)  |
                      ((v1.z >= 0.0f ? 0x38u : 0xB8u) << 16) |
                      ((v1.w >= 0.0f ? 0x38u : 0xB8u) << 24);
        *reinterpret_cast<uint2*>(g_xq + base) = make_uint2(lo, hi);
    } else {
        // fragment order: u4 = ((tap*32 + g)*2 + kk)*32 + lane   (R6 layout)
        //   outch o = g*8 + (lane>>2)
        //   {x,y} = B-frag regs for k=2kk, {z,w} for k=2kk+1 (m16n8k32 colB)
        int u = (blockIdx.x - X_BLOCKS) * 256 + threadIdx.x;
        if (u >= WF_U4) return;
        int lane = u & 31;
        int kk   = (u >> 5) & 1;
        int g    = (u >> 6) & 31;
        int tap  = u >> 11;
        int o = g * 8 + (lane >> 2);
        uint32_t r[4];
        #pragma unroll
        for (int kp = 0; kp < 2; ++kp) {
            int cb = (2 * kk + kp) * 32 + (lane & 3) * 4;
            uint32_t r0 = 0, r1 = 0;
            #pragma unroll
            for (int b2 = 0; b2 < 4; ++b2) {
                float v0 = w[(tap * 128 + cb + b2) * 256 + o];       // HWIO
                float v1 = w[(tap * 128 + cb + 16 + b2) * 256 + o];
                r0 |= (v0 >= 0.0f ? 0x38u : 0xB8u) << (8 * b2);
                r1 |= (v1 >= 0.0f ? 0x38u : 0xB8u) << (8 * b2);
            }
            r[2 * kp] = r0; r[2 * kp + 1] = r1;
        }
        g_wf[u] = make_uint4(r[0], r[1], r[2], r[3]);
    }
}

// ---------------------------------------------------------------------------
// PTX helpers
// ---------------------------------------------------------------------------
static __device__ __forceinline__ void ldmatrix_x4(uint32_t& r0, uint32_t& r1,
                                                   uint32_t& r2, uint32_t& r3,
                                                   uint32_t addr) {
    asm volatile("ldmatrix.sync.aligned.m8n8.x4.shared.b16 {%0,%1,%2,%3}, [%4];"
                 : "=r"(r0), "=r"(r1), "=r"(r2), "=r"(r3) : "r"(addr));
}

// fp8 MMA with f16 accumulators (2 regs, exact for integer sums < 2048)
static __device__ __forceinline__ void mma_fp8_h(uint32_t* c, const uint32_t* a,
                                                 uint32_t b0, uint32_t b1) {
    asm volatile(
        "mma.sync.aligned.m16n8k32.row.col.f16.e4m3.e4m3.f16 "
        "{%0,%1}, {%2,%3,%4,%5}, {%6,%7}, {%0,%1};"
        : "+r"(c[0]), "+r"(c[1])
        : "r"(a[0]), "r"(a[1]), "r"(a[2]), "r"(a[3]), "r"(b0), "r"(b1));
}

static __device__ __forceinline__ void cp16(uint32_t dst, const void* src, int srcsize) {
    asm volatile("cp.async.cg.shared.global [%0], [%1], 16, %2;"
                 :: "r"(dst), "l"(src), "r"(srcsize) : "memory");
}

// ---------------------------------------------------------------------------
// main kernel: 256 threads, 8 warps (4M x 2N), warp tile 32x64
// SMEM: A halo, 180 rows x 144B stride (128B data + 16B pad) = 25,920 B
// ---------------------------------------------------------------------------
constexpr int ROWB = 144;
constexpr int SMEM_TOTAL = 180 * ROWB;        // 25,920

__global__ void __launch_bounds__(256, 3)
conv_fp8_kernel(float* __restrict__ out) {
    extern __shared__ char smem[];
    uint32_t sbase = (uint32_t)__cvta_generic_to_shared(smem);

    int tid  = threadIdx.x;
    int lane = tid & 31;
    int wid  = tid >> 5;
    int warp_m = wid >> 1;       // 0..3 -> 32 pixel rows each
    int warp_n = wid & 1;        // 0..1 -> 64 outch each

    // tile decode: blockIdx = ((img*28 + ht*4 + wt) << 1) | ntile
    int b = blockIdx.x;
    int ntile = b & 1;
    int mt = b >> 1;
    int img = mt / 28;
    int rr  = mt - img * 28;
    int h0 = (rr >> 2) * 8;
    int w0 = (rr & 3) * 16;
    int n0 = ntile * 128;

    // ---- stage A halo (10h x 18w pixels, zero-filled outside image) ----
    for (int idx = tid; idx < 1440; idx += 256) {        // 180 rows x 8 chunks
        int row = idx >> 3, ch = idx & 7;
        int hr = row / 18;
        int wc = row - hr * 18;
        int hh = h0 + hr - 1;
        int ww = w0 + wc - 1;
        bool v = ((unsigned)hh < 56u) && ((unsigned)ww < 56u);
        const char* src = v ? (const char*)(g_xq + (((img * 56 + hh) * 56 + ww) << 7))
                            : (const char*)g_xq;
        cp16(sbase + row * ROWB + ch * 16, src + ch * 16, v ? 16 : 0);
    }
    asm volatile("cp.async.commit_group;" ::: "memory");
    asm volatile("cp.async.wait_group 0;" ::: "memory");
    __syncthreads();

    // ---- per-lane ldmatrix base addresses (linear: no xor in mainloop) ----
    int lane15 = lane & 15;
    int lanehi = lane >> 4;
    uint32_t abase[2];
    #pragma unroll
    for (int mi = 0; mi < 2; ++mi) {
        int p = warp_m * 32 + mi * 16 + lane15;          // pixel index 0..127
        int hrow = (p >> 4) * 18 + (p & 15);             // halo row at tap (0,0)
        abase[mi] = sbase + hrow * ROWB + lanehi * 16;
    }
    // B fragment base for this thread: g = ntile*16 + warp_n*8 + ni
    const uint4* wf0 = g_wf + (uint32_t)(((ntile * 16 + warp_n * 8) * 2) * 32 + lane);

    uint32_t acc[2][8][2];                               // f16x2 accumulators
    #pragma unroll
    for (int mi = 0; mi < 2; ++mi)
        #pragma unroll
        for (int ni = 0; ni < 8; ++ni) {
            acc[mi][ni][0] = 0u; acc[mi][ni][1] = 0u;
        }

    // ---- mainloop: 9 taps (ROLLED) x 2 kk, no barriers, no smem writes ----
    int tapoff = 0;   // kh*18 + kw
    int kw = 0;
    for (int tap = 0; tap < 9; ++tap) {
        const uint4* wft = wf0 + (uint32_t)(tap * 64 * 32);
        uint32_t atap0 = abase[0] + (uint32_t)(tapoff * ROWB);
        uint32_t atap1 = abase[1] + (uint32_t)(tapoff * ROWB);
        #pragma unroll
        for (int kk = 0; kk < 2; ++kk) {
            uint32_t a[2][2][4];                          // [kpar][mi][4]
            #pragma unroll
            for (int kp = 0; kp < 2; ++kp) {
                uint32_t koff = (uint32_t)((2 * kk + kp) * 32);  // LDSM immediate
                ldmatrix_x4(a[kp][0][0], a[kp][0][1], a[kp][0][2], a[kp][0][3],
                            atap0 + koff);
                ldmatrix_x4(a[kp][1][0], a[kp][1][1], a[kp][1][2], a[kp][1][3],
                            atap1 + koff);
            }
            const uint4* wfk = wft + (uint32_t)(kk * 32);
            #pragma unroll
            for (int ni = 0; ni < 8; ++ni) {
                uint4 bv = __ldg(wfk + ni * 64);          // g stride = 2*32 u4
                mma_fp8_h(acc[0][ni], a[0][0], bv.x, bv.y);
                mma_fp8_h(acc[1][ni], a[0][1], bv.x, bv.y);
                mma_fp8_h(acc[0][ni], a[1][0], bv.z, bv.w);
                mma_fp8_h(acc[1][ni], a[1][1], bv.z, bv.w);
            }
        }
        if (kw == 2) { kw = 0; tapoff += 16; }           // +18 - 2
        else         { kw++;   tapoff += 1;  }
    }

    // ---- epilogue: f16x2 -> f32 stores (exact, values are ints <= 1152) ----
    int colbase = n0 + warp_n * 64 + (lane & 3) * 2;
    #pragma unroll
    for (int mi = 0; mi < 2; ++mi) {
        #pragma unroll
        for (int half = 0; half < 2; ++half) {
            int p = warp_m * 32 + mi * 16 + half * 8 + (lane >> 2);
            int j = p & 15;
            int ww = w0 + j;
            if (ww >= 56) continue;
            int hh = h0 + (p >> 4);
            float* op = out + (((img * 56 + hh) * 56 + ww) << 8);
            #pragma unroll
            for (int ni = 0; ni < 8; ++ni) {
                __half2 h = *reinterpret_cast<__half2*>(&acc[mi][ni][half]);
                float2 v = __half22float2(h);
                *reinterpret_cast<float2*>(op + colbase + ni * 8) = v;
            }
        }
    }
}

// ---------------------------------------------------------------------------
// launch
// ---------------------------------------------------------------------------
extern "C" void kernel_launch(void* const* d_in, const int* in_sizes, int n_in,
                              void* d_out, int out_size) {
    const float* x = (const float*)d_in[0];
    const float* w = (const float*)d_in[1];
    float* out = (float*)d_out;

    prep_kernel<<<X_BLOCKS + (WF_U4 + 255) / 256, 256>>>(x, w);

    cudaFuncSetAttribute(conv_fp8_kernel,
                         cudaFuncAttributeMaxDynamicSharedMemorySize, SMEM_TOTAL);
    // 64 images * 7 h-tiles * 4 w-tiles * 2 n-tiles = 3584 CTAs
    conv_fp8_kernel<<<3584, 256, SMEM_TOTAL>>>(out);
}